// round 2
// baseline (speedup 1.0000x reference)
#include <cuda_runtime.h>

#define NFLAT 1056768   /* 32*256*129 */
#define PLANE 33024     /* 256*129 */

__device__ float2 d_W[256];
__device__ float  d_G[3*5*9*9*2];   // [c][k2][g0][g1][re/im]

__global__ void build_kernel(const float* __restrict__ seeds,
                             const float* __restrict__ Pk,
                             const float* __restrict__ defscale,
                             const int*  __restrict__ feed_idx,
                             int fdim) {
    int t = threadIdx.x;
    if (t < 256) {
        float s, c;
        sincospif((float)t / 128.0f, &s, &c);
        d_W[t] = make_float2(c, s);
    }
    for (int i = t; i < 3*5*9*9*2; i += blockDim.x) d_G[i] = 0.0f;
    __syncthreads();
    const float inv_n = 1.0f / 2097152.0f;   // 1/prod(REALSHAPE): irfftn normalization
    for (int j = t; j < fdim; j += blockDim.x) {
        int flat = feed_idx[j];
        int part = flat / NFLAT;             // 0 = re, 1 = im
        int r = flat - part * NFLAT;
        int k0 = r / PLANE; r -= k0 * PLANE;
        int k1 = r / 129;
        int k2 = r - k1 * 129;
        int f0 = (k0 <= 16) ? k0 : k0 - 32;  // |f0| <= 4 guaranteed by ksq<=16
        int f1 = (k1 <= 128) ? k1 : k1 - 256;
        float w = (k0 == 0 && k1 == 0 && k2 == 0) ? 1.0f : 2.0f;  // DC counted once
        float base = Pk[j] * w * inv_n;
        int slot = ((k2 * 9 + (f0 + 4)) * 9 + (f1 + 4)) * 2 + part;
        for (int c = 0; c < 3; c++) {
            float a = seeds[c * fdim + j] * defscale[c] * base;
            d_G[c * (5*9*9*2) + slot] = a;   // unique slot per (c,part,k): plain store
        }
    }
}

__global__ void __launch_bounds__(256) deform_kernel(const float* __restrict__ fr,
                                                     float* __restrict__ out) {
    __shared__ float2 sW[256];
    __shared__ float2 sP[135];
    __shared__ float2 sH[15];
    int tid = threadIdx.x;
    int i1 = blockIdx.x;
    int i0 = blockIdx.y;
    sW[tid] = d_W[tid];
    __syncthreads();

    // Fold (k0,k1) for this (i0,i1) row: 135 threads each sum 9 k1-terms
    if (tid < 135) {
        int c   = tid / 45;
        int rem = tid - c * 45;
        int k2  = rem / 9;
        int g0  = rem - k2 * 9;
        int f0  = g0 - 4;
        int t0  = (8 * f0 * i0 + 4096) & 255;
        float2 acc = make_float2(0.f, 0.f);
        const float* Gp = d_G + ((c * 5 + k2) * 9 + g0) * 9 * 2;
        #pragma unroll
        for (int g1 = 0; g1 < 9; g1++) {
            int f1 = g1 - 4;
            int tt = (t0 + f1 * i1 + 4096) & 255;
            float gr = Gp[g1 * 2 + 0], gi = Gp[g1 * 2 + 1];
            float2 wv = sW[tt];
            acc.x += gr * wv.x - gi * wv.y;
            acc.y += gr * wv.y + gi * wv.x;
        }
        sP[tid] = acc;
    }
    __syncthreads();
    if (tid < 15) {
        int c = tid / 5, k2 = tid - c * 5;
        float2 h = make_float2(0.f, 0.f);
        int base = c * 45 + k2 * 9;
        #pragma unroll
        for (int g0 = 0; g0 < 9; g0++) { h.x += sP[base + g0].x; h.y += sP[base + g0].y; }
        sH[tid] = h;
    }
    __syncthreads();

    // Per-thread displacement: disp_c = Re( sum_k2 H[c][k2] * e^{2*pi*i*k2*i2/256} )
    int i2 = tid;
    float d0, d1, d2;
    {
        float dd[3];
        #pragma unroll
        for (int c = 0; c < 3; c++) {
            float acc = 0.f;
            #pragma unroll
            for (int k2 = 0; k2 < 5; k2++) {
                int tt = (k2 * i2) & 255;
                float2 h = sH[c * 5 + k2];
                float2 wv = sW[tt];
                acc += h.x * wv.x - h.y * wv.y;
            }
            dd[c] = acc;
        }
        d0 = dd[0]; d1 = dd[1]; d2 = dd[2];
    }

    // grid_sample: bilinear, border clamp, align_corners=True -> sample at i - disp
    float fz = fminf(fmaxf((float)i0 - d0, 0.f), 31.f);
    float fy = fminf(fmaxf((float)i1 - d1, 0.f), 255.f);
    float fx = fminf(fmaxf((float)i2 - d2, 0.f), 255.f);
    int z0 = (int)fz, y0 = (int)fy, x0 = (int)fx;
    float wz = fz - (float)z0, wy = fy - (float)y0, wx = fx - (float)x0;
    int z1 = min(z0 + 1, 31), y1 = min(y0 + 1, 255), x1 = min(x0 + 1, 255);

    int o00 = z0 * 65536 + y0 * 256;
    int o01 = z0 * 65536 + y1 * 256;
    int o10 = z1 * 65536 + y0 * 256;
    int o11 = z1 * 65536 + y1 * 256;
    int pix = i0 * 65536 + i1 * 256 + i2;

    float iwx = 1.f - wx, iwy = 1.f - wy, iwz = 1.f - wz;

    #pragma unroll
    for (int bc = 0; bc < 12; bc++) {
        const float* p = fr + (size_t)bc * 2097152;
        float v000 = __ldg(p + o00 + x0);
        float v001 = __ldg(p + o00 + x1);
        float v010 = __ldg(p + o01 + x0);
        float v011 = __ldg(p + o01 + x1);
        float v100 = __ldg(p + o10 + x0);
        float v101 = __ldg(p + o10 + x1);
        float v110 = __ldg(p + o11 + x0);
        float v111 = __ldg(p + o11 + x1);
        float c00 = v000 * iwx + v001 * wx;
        float c01 = v010 * iwx + v011 * wx;
        float c10 = v100 * iwx + v101 * wx;
        float c11 = v110 * iwx + v111 * wx;
        float c0 = c00 * iwy + c01 * wy;
        float c1 = c10 * iwy + c11 * wy;
        out[(size_t)bc * 2097152 + pix] = c0 * iwz + c1 * wz;
    }
}

extern "C" void kernel_launch(void* const* d_in, const int* in_sizes, int n_in,
                              void* d_out, int out_size) {
    const float* fr       = (const float*)d_in[0];
    const float* seeds    = (const float*)d_in[1];
    const float* Pk       = (const float*)d_in[2];
    const float* defscale = (const float*)d_in[3];
    const int*   feed_idx = (const int*)d_in[5];
    int fdim = in_sizes[5];

    build_kernel<<<1, 256>>>(seeds, Pk, defscale, feed_idx, fdim);
    dim3 g(256, 32);
    deform_kernel<<<g, 256>>>(fr, (float*)d_out);
}